// round 1
// baseline (speedup 1.0000x reference)
#include <cuda_runtime.h>
#include <cstdint>

// Problem constants (fixed by the dataset)
#define N_NODES 25000
#define N_EDGES 400000
#define F_DIM   128
#define S_DIM   256
#define L_DIM   64
#define ROUNDS  4

// ---------------------------------------------------------------------------
// Scratch (device globals; no allocation anywhere)
// ---------------------------------------------------------------------------
__device__ float g_state[(size_t)N_NODES * S_DIM];   // 25.6 MB
__device__ float g_P[(size_t)N_NODES * S_DIM];       // 25.6 MB
__device__ float g_Q[(size_t)N_NODES * S_DIM];       // 25.6 MB
__device__ int   g_counts[N_NODES];
__device__ int   g_row_ptr[N_NODES + 1];
__device__ int   g_cursor[N_NODES];
__device__ int   g_col_src[N_EDGES];

// ---------------------------------------------------------------------------
// CSR construction (dest-sorted incoming-edge lists)
// ---------------------------------------------------------------------------
__global__ void zero_counts_kernel() {
    int i = blockIdx.x * blockDim.x + threadIdx.x;
    if (i < N_NODES) g_counts[i] = 0;
}

__global__ void hist_kernel(const int* __restrict__ dest) {
    int e = blockIdx.x * blockDim.x + threadIdx.x;
    if (e < N_EDGES) atomicAdd(&g_counts[dest[e]], 1);
}

// Single-block exclusive scan over g_counts -> g_row_ptr (len N_NODES+1), g_cursor
__global__ void __launch_bounds__(1024) scan_kernel() {
    __shared__ int temp[1024];
    __shared__ int carry_s;
    if (threadIdx.x == 0) { carry_s = 0; g_row_ptr[0] = 0; }
    __syncthreads();
    for (int base = 0; base < N_NODES; base += 1024) {
        int i = base + (int)threadIdx.x;
        int v = (i < N_NODES) ? g_counts[i] : 0;
        temp[threadIdx.x] = v;
        __syncthreads();
        // Hillis-Steele inclusive scan
        for (int off = 1; off < 1024; off <<= 1) {
            int t = 0;
            if (threadIdx.x >= (unsigned)off) t = temp[threadIdx.x - off];
            __syncthreads();
            temp[threadIdx.x] += t;
            __syncthreads();
        }
        int incl = temp[threadIdx.x];
        int carry = carry_s;
        if (i < N_NODES) {
            g_row_ptr[i + 1] = carry + incl;
            g_cursor[i]      = carry + incl - v;  // exclusive prefix
        }
        __syncthreads();
        if (threadIdx.x == 1023) carry_s = carry + temp[1023];
        __syncthreads();
    }
}

__global__ void fill_kernel(const int* __restrict__ src, const int* __restrict__ dest) {
    int e = blockIdx.x * blockDim.x + threadIdx.x;
    if (e < N_EDGES) {
        int d   = dest[e];
        int pos = atomicAdd(&g_cursor[d], 1);
        g_col_src[pos] = src[e];
    }
}

// ---------------------------------------------------------------------------
// SIMT fp32 GEMM: C[M,N] = A[M,K] @ B[K,N] (+bias)(+relu)
// BM=128 BN=64 BK=16, 256 threads, 8x4 per thread.
// Requires: K % 16 == 0, N % 64 == 0.
// ---------------------------------------------------------------------------
template <bool RELU, bool BIAS>
__global__ void __launch_bounds__(256) sgemm_kernel(
    const float* __restrict__ A, const float* __restrict__ B,
    const float* __restrict__ bias, float* __restrict__ C,
    int M, int N, int K)
{
    constexpr int BM = 128, BN = 64, BK = 16, TM = 8, TN = 4;
    __shared__ float As[BK][BM];
    __shared__ float Bs[BK][BN];

    const int tid = threadIdx.x;
    const int bm  = blockIdx.y * BM;
    const int bn  = blockIdx.x * BN;
    const int ty  = tid / 16;       // 0..15
    const int tx  = tid % 16;       // 0..15

    // A tile load: 128x16 floats; each thread: 2x float4
    const int arow = tid >> 2;           // 0..63
    const int acol = (tid & 3) << 2;     // 0,4,8,12
    // B tile load: 16x64 floats; each thread: 1x float4
    const int brow = tid >> 4;           // 0..15
    const int bcol = (tid & 15) << 2;    // 0..60

    float acc[TM][TN];
#pragma unroll
    for (int i = 0; i < TM; i++)
#pragma unroll
        for (int j = 0; j < TN; j++) acc[i][j] = 0.f;

    for (int k0 = 0; k0 < K; k0 += BK) {
#pragma unroll
        for (int h = 0; h < 2; h++) {
            int r  = arow + h * 64;
            int gm = bm + r;
            float4 v = make_float4(0.f, 0.f, 0.f, 0.f);
            if (gm < M) v = *(const float4*)(A + (size_t)gm * K + k0 + acol);
            As[acol + 0][r] = v.x;
            As[acol + 1][r] = v.y;
            As[acol + 2][r] = v.z;
            As[acol + 3][r] = v.w;
        }
        {
            float4 v = *(const float4*)(B + (size_t)(k0 + brow) * N + bn + bcol);
            Bs[brow][bcol + 0] = v.x;
            Bs[brow][bcol + 1] = v.y;
            Bs[brow][bcol + 2] = v.z;
            Bs[brow][bcol + 3] = v.w;
        }
        __syncthreads();

#pragma unroll
        for (int kk = 0; kk < BK; kk++) {
            float ra[TM], rb[TN];
            // LDS.128 loads (aligned)
            float4 a0 = *(const float4*)&As[kk][ty * TM];
            float4 a1 = *(const float4*)&As[kk][ty * TM + 4];
            ra[0] = a0.x; ra[1] = a0.y; ra[2] = a0.z; ra[3] = a0.w;
            ra[4] = a1.x; ra[5] = a1.y; ra[6] = a1.z; ra[7] = a1.w;
            float4 b0 = *(const float4*)&Bs[kk][tx * TN];
            rb[0] = b0.x; rb[1] = b0.y; rb[2] = b0.z; rb[3] = b0.w;
#pragma unroll
            for (int i = 0; i < TM; i++)
#pragma unroll
                for (int j = 0; j < TN; j++)
                    acc[i][j] = fmaf(ra[i], rb[j], acc[i][j]);
        }
        __syncthreads();
    }

    // Epilogue
    float bv[TN];
#pragma unroll
    for (int j = 0; j < TN; j++)
        bv[j] = BIAS ? bias[bn + tx * TN + j] : 0.f;

#pragma unroll
    for (int i = 0; i < TM; i++) {
        int gm = bm + ty * TM + i;
        if (gm < M) {
            float4 o;
            float v0 = acc[i][0] + bv[0];
            float v1 = acc[i][1] + bv[1];
            float v2 = acc[i][2] + bv[2];
            float v3 = acc[i][3] + bv[3];
            if (RELU) {
                v0 = fmaxf(v0, 0.f); v1 = fmaxf(v1, 0.f);
                v2 = fmaxf(v2, 0.f); v3 = fmaxf(v3, 0.f);
            }
            o.x = v0; o.y = v1; o.z = v2; o.w = v3;
            *(float4*)(C + (size_t)gm * N + bn + tx * TN) = o;
        }
    }
}

// ---------------------------------------------------------------------------
// Fused message + segment-sum + state update.
// One block (256 threads, 1 channel/thread) per node:
//   state[n] += sum_{e in in(n)} relu(P[src[e]] + Q[n] + b)
// ---------------------------------------------------------------------------
__global__ void __launch_bounds__(256) aggregate_kernel(const float* __restrict__ bias) {
    const int n = blockIdx.x;
    const int c = threadIdx.x;

    const int beg = g_row_ptr[n];
    const int end = g_row_ptr[n + 1];

    const size_t nofs = (size_t)n * S_DIM + c;
    const float q   = g_Q[nofs] + bias[c];
    float acc       = g_state[nofs];

    int e = beg;
    for (; e + 4 <= end; e += 4) {
        int s0 = g_col_src[e + 0];
        int s1 = g_col_src[e + 1];
        int s2 = g_col_src[e + 2];
        int s3 = g_col_src[e + 3];
        float p0 = g_P[(size_t)s0 * S_DIM + c];
        float p1 = g_P[(size_t)s1 * S_DIM + c];
        float p2 = g_P[(size_t)s2 * S_DIM + c];
        float p3 = g_P[(size_t)s3 * S_DIM + c];
        acc += fmaxf(p0 + q, 0.f);
        acc += fmaxf(p1 + q, 0.f);
        acc += fmaxf(p2 + q, 0.f);
        acc += fmaxf(p3 + q, 0.f);
    }
    for (; e < end; e++) {
        int s = g_col_src[e];
        acc += fmaxf(g_P[(size_t)s * S_DIM + c] + q, 0.f);
    }
    g_state[nofs] = acc;
}

// ---------------------------------------------------------------------------
// Launch
// ---------------------------------------------------------------------------
extern "C" void kernel_launch(void* const* d_in, const int* in_sizes, int n_in,
                              void* d_out, int out_size)
{
    (void)in_sizes; (void)n_in; (void)out_size;

    const float* x          = (const float*)d_in[0];  // [25000,128]
    const int*   edge_index = (const int*)  d_in[1];  // [2,400000]
    // d_in[2] = batch (unused by reference)
    const float* W_in  = (const float*)d_in[3];       // [128,256]
    const float* b_in  = (const float*)d_in[4];       // [256]
    const float* W_msg = (const float*)d_in[5];       // [4,512,256]
    const float* b_msg = (const float*)d_in[6];       // [4,256]
    const float* W_out = (const float*)d_in[7];       // [256,64]
    const float* b_out = (const float*)d_in[8];       // [64]
    float* out = (float*)d_out;                       // [25000,64]

    const int* src  = edge_index;
    const int* dest = edge_index + N_EDGES;

    void *p_state, *p_P, *p_Q;
    cudaGetSymbolAddress(&p_state, g_state);
    cudaGetSymbolAddress(&p_P, g_P);
    cudaGetSymbolAddress(&p_Q, g_Q);
    float* state = (float*)p_state;
    float* P     = (float*)p_P;
    float* Q     = (float*)p_Q;

    const int EB = (N_EDGES + 255) / 256;
    const int NB = (N_NODES + 255) / 256;

    // --- CSR build (dest is identical every call; rebuilt for determinism) ---
    zero_counts_kernel<<<NB, 256>>>();
    hist_kernel<<<EB, 256>>>(dest);
    scan_kernel<<<1, 1024>>>();
    fill_kernel<<<EB, 256>>>(src, dest);

    // --- input net: state = relu(x @ W_in + b_in) ---
    {
        dim3 grid(S_DIM / 64, (N_NODES + 127) / 128);
        sgemm_kernel<true, true><<<grid, 256>>>(x, W_in, b_in, state,
                                                N_NODES, S_DIM, F_DIM);
    }

    // --- message rounds ---
    for (int r = 0; r < ROUNDS; r++) {
        const float* Wr = W_msg + (size_t)r * 2 * S_DIM * S_DIM;
        dim3 grid(S_DIM / 64, (N_NODES + 127) / 128);
        // P = state @ W_msg[r][0:256,:]
        sgemm_kernel<false, false><<<grid, 256>>>(state, Wr, nullptr, P,
                                                  N_NODES, S_DIM, S_DIM);
        // Q = state @ W_msg[r][256:512,:]
        sgemm_kernel<false, false><<<grid, 256>>>(state, Wr + (size_t)S_DIM * S_DIM,
                                                  nullptr, Q,
                                                  N_NODES, S_DIM, S_DIM);
        // state[n] += sum relu(P[src] + Q[n] + b_msg[r])
        aggregate_kernel<<<N_NODES, 256>>>(b_msg + (size_t)r * S_DIM);
    }

    // --- output net: out = state @ W_out + b_out ---
    {
        dim3 grid(L_DIM / 64, (N_NODES + 127) / 128);
        sgemm_kernel<false, true><<<grid, 256>>>(state, W_out, b_out, out,
                                                 N_NODES, L_DIM, S_DIM);
    }
}